// round 13
// baseline (speedup 1.0000x reference)
#include <cuda_runtime.h>
#include <cuda_bf16.h>

// bow_labeler: masked mean-pool over L, then 14 small linear heads (54 outputs).
// B=256, L=512, D=768.
// SINGLE pass, algebraically fused: the heads are linear, so
//   out[b,o] = sum_s (partial[b,s] . w[o]) / cnt_b + bias[o].
// Each streamer block (b, s) computes masked partial column sums for its
// 64-row chunk ENTIRELY in smem (no global partial buffer), then computes the
// 54 dot products against L1-resident weights and atomicAdds the scaled
// scalars into out. No inter-block sync, no fences, no second kernel.
// out is zeroed by a captured memset node; bias is added by the s==0 block.

#define B_DIM   256
#define L_DIM   512
#define D_DIM   768
#define N_OUT   54
#define SPLIT   8
#define L_CHUNK (L_DIM / SPLIT)   // 64
#define D4      (D_DIM / 4)       // 192 float4 per row
#define NT      192               // one thread per float4 column
#define NWARP   (NT / 32)         // 6 warps, 9 outputs each

__device__ __forceinline__ void f4acc(float4& a, const float4& v) {
    a.x += v.x; a.y += v.y; a.z += v.z; a.w += v.w;
}

__global__ __launch_bounds__(NT) void bow_fused_linear_kernel(
    const float* __restrict__ fh,
    const int*   __restrict__ mask,
    const float* __restrict__ W13,
    const float* __restrict__ b13,
    const float* __restrict__ W14,
    const float* __restrict__ b14,
    float*       __restrict__ out)
{
    const int s    = blockIdx.x;
    const int b    = blockIdx.y;
    const int tid  = threadIdx.x;   // float4 column 0..191
    const int lane = tid & 31;
    const int warp = tid >> 5;

    __shared__ int    s_mask[L_CHUNK];
    __shared__ float4 s_part[D4];   // 3 KB: this block's partial sums
    __shared__ int    s_cnt;
    __shared__ float  s_inv;

    if (tid == 0) s_cnt = 0;
    if (tid < L_CHUNK) s_mask[tid] = mask[b * L_DIM + s * L_CHUNK + tid];
    __syncthreads();

    // Per-batch valid-token count (needed by every block for the 1/cnt scale).
    // Mask row is 2 KB, L2/L1-resident after first touch.
    {
        const int* mrow = mask + b * L_DIM;
        int m = mrow[tid] + mrow[tid + 192] + ((tid < 128) ? mrow[tid + 384] : 0);
        #pragma unroll
        for (int off = 16; off; off >>= 1)
            m += __shfl_down_sync(0xffffffffu, m, off);
        if (lane == 0) atomicAdd(&s_cnt, m);
    }

    // Masked partial column sums over the 64-row chunk: predicated 8-deep
    // float4 loads (measured-best streaming form, ~5.4 TB/s valid traffic).
    const float4* base =
        (const float4*)(fh + ((size_t)b * L_DIM + (size_t)s * L_CHUNK) * D_DIM) + tid;

    float4 a0 = make_float4(0.f,0.f,0.f,0.f);
    float4 a1 = make_float4(0.f,0.f,0.f,0.f);
    float4 a2 = make_float4(0.f,0.f,0.f,0.f);
    float4 a3 = make_float4(0.f,0.f,0.f,0.f);
    #pragma unroll 1
    for (int l = 0; l < L_CHUNK; l += 8) {
        if (s_mask[l+0]) f4acc(a0, base[(size_t)(l+0) * D4]);
        if (s_mask[l+1]) f4acc(a1, base[(size_t)(l+1) * D4]);
        if (s_mask[l+2]) f4acc(a2, base[(size_t)(l+2) * D4]);
        if (s_mask[l+3]) f4acc(a3, base[(size_t)(l+3) * D4]);
        if (s_mask[l+4]) f4acc(a0, base[(size_t)(l+4) * D4]);
        if (s_mask[l+5]) f4acc(a1, base[(size_t)(l+5) * D4]);
        if (s_mask[l+6]) f4acc(a2, base[(size_t)(l+6) * D4]);
        if (s_mask[l+7]) f4acc(a3, base[(size_t)(l+7) * D4]);
    }
    f4acc(a0, a1); f4acc(a2, a3); f4acc(a0, a2);
    s_part[tid] = a0;

    __syncthreads();
    if (tid == 0) s_inv = 1.0f / (float)s_cnt;
    __syncthreads();

    // 54 dot products of this partial against the head weights (L1-resident
    // after the first block on each SM), scaled by 1/cnt, atomically
    // accumulated into out. Bias contributed exactly once (s == 0).
    const float inv = s_inv;
    for (int o = warp; o < N_OUT; o += NWARP) {
        const float4* w4 = (const float4*)((o < 52) ? (W13 + (size_t)o * D_DIM)
                                                    : (W14 + (size_t)(o - 52) * D_DIM));
        float acc = 0.f;
        #pragma unroll
        for (int i = 0; i < D4 / 32; i++) {
            float4 w = w4[lane + 32 * i];
            float4 p = s_part[lane + 32 * i];
            acc += w.x * p.x + w.y * p.y + w.z * p.z + w.w * p.w;
        }
        #pragma unroll
        for (int off = 16; off; off >>= 1)
            acc += __shfl_down_sync(0xffffffffu, acc, off);
        if (lane == 0) {
            float contrib = acc * inv;
            if (s == 0) contrib += (o < 52) ? b13[o] : b14[o - 52];
            atomicAdd(&out[b * N_OUT + o], contrib);
        }
    }
}

extern "C" void kernel_launch(void* const* d_in, const int* in_sizes, int n_in,
                              void* d_out, int out_size)
{
    const float* fh   = (const float*)d_in[0];
    const int*   mask = (const int*)d_in[1];
    const float* W13  = (const float*)d_in[2];
    const float* b13  = (const float*)d_in[3];
    const float* W14  = (const float*)d_in[4];
    const float* b14  = (const float*)d_in[5];
    float* out = (float*)d_out;

    // Zero the accumulator output (captured as a memset node; no allocation).
    cudaMemsetAsync(out, 0, (size_t)out_size * sizeof(float), 0);

    dim3 grid(SPLIT, B_DIM);
    bow_fused_linear_kernel<<<grid, NT>>>(fh, mask, W13, b13, W14, b14, out);
}

// round 14
// speedup vs baseline: 1.9624x; 1.9624x over previous
#include <cuda_runtime.h>
#include <cuda_bf16.h>

// bow_labeler: masked mean-pool over L, then 14 small linear heads (54 outputs).
// B=256, L=512, D=768.
// K1: masked partial column sums, predicated 8-deep float4 loads
//     (measured wall ~5.4 TB/s on valid traffic for this skip pattern).
// K2: reduce 8 partials + count + normalize -> g_pooled (PDL; mask count
//     overlapped under K1's tail).
// K3: heads GEMV, grid (64 batch-groups x 7 output-groups) = 448 blocks x
//     256 thr, one output per warp, 4 batches per warp, register weights
//     (PDL; weight loads overlapped under K2).

#define B_DIM   256
#define L_DIM   512
#define D_DIM   768
#define N_OUT   54
#define SPLIT   8
#define L_CHUNK (L_DIM / SPLIT)   // 64
#define D4      (D_DIM / 4)       // 192 float4 per row
#define T1      192
#define T2      192
#define T3      256               // 8 warps
#define BPB     4                 // batches per heads block
#define NBG     (B_DIM / BPB)     // 64 batch groups
#define OGRP    7                 // output groups
#define OPG     8                 // outputs per group (last group: 6)

__device__ float g_partial[B_DIM * SPLIT * D_DIM];   // 6 MB
__device__ float g_pooled[B_DIM * D_DIM];            // 0.75 MB

__device__ __forceinline__ void f4acc(float4& a, const float4& v) {
    a.x += v.x; a.y += v.y; a.z += v.z; a.w += v.w;
}

// ---------------- K1: masked partial sums ----------------
__global__ __launch_bounds__(T1) void pool_partial_kernel(
    const float* __restrict__ fh,
    const int*   __restrict__ mask)
{
    const int s  = blockIdx.x;
    const int b  = blockIdx.y;
    const int c4 = threadIdx.x;   // float4 column 0..191

    __shared__ int s_mask[L_CHUNK];
    if (c4 < L_CHUNK) s_mask[c4] = mask[b * L_DIM + s * L_CHUNK + c4];
    __syncthreads();

    const float4* base =
        (const float4*)(fh + ((size_t)b * L_DIM + (size_t)s * L_CHUNK) * D_DIM) + c4;

    float4 a0 = make_float4(0.f,0.f,0.f,0.f);
    float4 a1 = make_float4(0.f,0.f,0.f,0.f);
    float4 a2 = make_float4(0.f,0.f,0.f,0.f);
    float4 a3 = make_float4(0.f,0.f,0.f,0.f);
    #pragma unroll 1
    for (int l = 0; l < L_CHUNK; l += 8) {
        if (s_mask[l+0]) f4acc(a0, base[(size_t)(l+0) * D4]);
        if (s_mask[l+1]) f4acc(a1, base[(size_t)(l+1) * D4]);
        if (s_mask[l+2]) f4acc(a2, base[(size_t)(l+2) * D4]);
        if (s_mask[l+3]) f4acc(a3, base[(size_t)(l+3) * D4]);
        if (s_mask[l+4]) f4acc(a0, base[(size_t)(l+4) * D4]);
        if (s_mask[l+5]) f4acc(a1, base[(size_t)(l+5) * D4]);
        if (s_mask[l+6]) f4acc(a2, base[(size_t)(l+6) * D4]);
        if (s_mask[l+7]) f4acc(a3, base[(size_t)(l+7) * D4]);
    }
    f4acc(a0, a1); f4acc(a2, a3); f4acc(a0, a2);

    ((float4*)(g_partial + ((size_t)b * SPLIT + s) * D_DIM))[c4] = a0;
}

// ---------------- K2: reduce partials + normalize (PDL secondary) ----------
__global__ __launch_bounds__(T2) void pool_reduce_kernel(
    const int* __restrict__ mask)
{
    const int b    = blockIdx.x;
    const int tid  = threadIdx.x;      // float4 column 0..191
    const int lane = tid & 31;

    __shared__ int   s_cnt;
    __shared__ float s_inv;

    if (tid == 0) s_cnt = 0;
    __syncthreads();

    // Pre-sync work (independent of K1): count valid tokens.
    {
        const int* mrow = mask + b * L_DIM;
        int m = mrow[tid] + mrow[tid + 192] + ((tid < 128) ? mrow[tid + 384] : 0);
        #pragma unroll
        for (int off = 16; off; off >>= 1)
            m += __shfl_down_sync(0xffffffffu, m, off);
        if (lane == 0) atomicAdd(&s_cnt, m);
    }

    cudaGridDependencySynchronize();

    const float4* gp4 = (const float4*)(g_partial + (size_t)b * SPLIT * D_DIM);
    float4 cs = make_float4(0.f,0.f,0.f,0.f);
    #pragma unroll
    for (int s = 0; s < SPLIT; s++)
        f4acc(cs, gp4[(size_t)s * D4 + tid]);

    __syncthreads();
    if (tid == 0) s_inv = 1.0f / (float)s_cnt;
    __syncthreads();

    float inv = s_inv;
    cs.x *= inv; cs.y *= inv; cs.z *= inv; cs.w *= inv;
    ((float4*)(g_pooled + (size_t)b * D_DIM))[tid] = cs;
}

// ---------------- K3: heads GEMV (PDL secondary) ----------------
__global__ __launch_bounds__(T3) void heads_kernel(
    const float* __restrict__ W13,
    const float* __restrict__ b13,
    const float* __restrict__ W14,
    const float* __restrict__ b14,
    float*       __restrict__ out)
{
    const int b0   = blockIdx.x * BPB;        // batch group
    const int og   = blockIdx.y;              // output group
    const int tid  = threadIdx.x;
    const int lane = tid & 31;
    const int warp = tid >> 5;                // 0..7

    __shared__ float4 s_pooled[BPB][D4];      // 12 KB

    const int o       = og * OPG + warp;
    const bool active = (o < N_OUT);

    // Pre-sync: weights into registers (overlaps K2).
    float4 w[D4 / 32];
    float  bias = 0.f;
    if (active) {
        const float4* w4 = (const float4*)((o < 52) ? (W13 + (size_t)o * D_DIM)
                                                    : (W14 + (size_t)(o - 52) * D_DIM));
        bias = (o < 52) ? b13[o] : b14[o - 52];
        #pragma unroll
        for (int i = 0; i < D4 / 32; i++) w[i] = w4[lane + 32 * i];
    }

    cudaGridDependencySynchronize();

    // Stage 4 pooled vectors (768 float4, 256 threads -> 3 loads each).
    #pragma unroll
    for (int k = 0; k < 3; k++) {
        int idx = tid + T3 * k;
        int bi = idx / D4, c4 = idx % D4;
        s_pooled[bi][c4] =
            ((const float4*)(g_pooled + (size_t)(b0 + bi) * D_DIM))[c4];
    }
    __syncthreads();

    if (!active) return;

    float acc[BPB] = {0.f, 0.f, 0.f, 0.f};
    #pragma unroll
    for (int i = 0; i < D4 / 32; i++) {
        #pragma unroll
        for (int bi = 0; bi < BPB; bi++) {
            float4 p = s_pooled[bi][lane + 32 * i];
            acc[bi] += w[i].x * p.x + w[i].y * p.y + w[i].z * p.z + w[i].w * p.w;
        }
    }
    #pragma unroll
    for (int off = 16; off; off >>= 1) {
        #pragma unroll
        for (int bi = 0; bi < BPB; bi++)
            acc[bi] += __shfl_down_sync(0xffffffffu, acc[bi], off);
    }
    if (lane == 0) {
        #pragma unroll
        for (int bi = 0; bi < BPB; bi++)
            out[(b0 + bi) * N_OUT + o] = acc[bi] + bias;
    }
}

extern "C" void kernel_launch(void* const* d_in, const int* in_sizes, int n_in,
                              void* d_out, int out_size)
{
    const float* fh   = (const float*)d_in[0];
    const int*   mask = (const int*)d_in[1];
    const float* W13  = (const float*)d_in[2];
    const float* b13  = (const float*)d_in[3];
    const float* W14  = (const float*)d_in[4];
    const float* b14  = (const float*)d_in[5];
    float* out = (float*)d_out;

    dim3 grid1(SPLIT, B_DIM);
    pool_partial_kernel<<<grid1, T1>>>(fh, mask);

    cudaLaunchAttribute attr[1];
    attr[0].id = cudaLaunchAttributeProgrammaticStreamSerialization;
    attr[0].val.programmaticStreamSerializationAllowed = 1;

    {   // K2 with PDL
        cudaLaunchConfig_t cfg = {};
        cfg.gridDim = dim3(B_DIM);
        cfg.blockDim = dim3(T2);
        cfg.attrs = attr;
        cfg.numAttrs = 1;
        cudaLaunchKernelEx(&cfg, pool_reduce_kernel, mask);
    }
    {   // K3 with PDL
        cudaLaunchConfig_t cfg = {};
        cfg.gridDim = dim3(NBG, OGRP);
        cfg.blockDim = dim3(T3);
        cfg.attrs = attr;
        cfg.numAttrs = 1;
        cudaLaunchKernelEx(&cfg, heads_kernel, W13, b13, W14, b14, out);
    }
}

// round 15
// speedup vs baseline: 1.9680x; 1.0028x over previous
#include <cuda_runtime.h>
#include <cuda_bf16.h>

// bow_labeler: masked mean-pool over L, then 14 small linear heads (54 outputs).
// B=256, L=512, D=768.
// K1: masked partial column sums, predicated 8-deep float4 loads
//     (measured wall ~5.4 TB/s on valid traffic for this skip pattern).
// K2: SINGLE fused epilogue (PDL on K1), grid (64 batch-groups x 7 output-
//     groups) = 448 blocks x 256 thr:
//       pre-sync : head weights -> registers, mask counts -> smem
//       post-sync: reduce 4 batches' 8 partials from L2, normalize,
//                  54-head GEMV (one output/warp, 4 batches/warp).

#define B_DIM   256
#define L_DIM   512
#define D_DIM   768
#define N_OUT   54
#define SPLIT   8
#define L_CHUNK (L_DIM / SPLIT)   // 64
#define D4      (D_DIM / 4)       // 192 float4 per row
#define T1      192
#define T3      256               // 8 warps
#define BPB     4                 // batches per epilogue block
#define NBG     (B_DIM / BPB)     // 64 batch groups
#define OGRP    7                 // output groups
#define OPG     8                 // outputs per group (last group: 6)

__device__ float g_partial[B_DIM * SPLIT * D_DIM];   // 6 MB

__device__ __forceinline__ void f4acc(float4& a, const float4& v) {
    a.x += v.x; a.y += v.y; a.z += v.z; a.w += v.w;
}

// ---------------- K1: masked partial sums ----------------
__global__ __launch_bounds__(T1) void pool_partial_kernel(
    const float* __restrict__ fh,
    const int*   __restrict__ mask)
{
    const int s  = blockIdx.x;
    const int b  = blockIdx.y;
    const int c4 = threadIdx.x;   // float4 column 0..191

    __shared__ int s_mask[L_CHUNK];
    if (c4 < L_CHUNK) s_mask[c4] = mask[b * L_DIM + s * L_CHUNK + c4];
    __syncthreads();

    const float4* base =
        (const float4*)(fh + ((size_t)b * L_DIM + (size_t)s * L_CHUNK) * D_DIM) + c4;

    float4 a0 = make_float4(0.f,0.f,0.f,0.f);
    float4 a1 = make_float4(0.f,0.f,0.f,0.f);
    float4 a2 = make_float4(0.f,0.f,0.f,0.f);
    float4 a3 = make_float4(0.f,0.f,0.f,0.f);
    #pragma unroll 1
    for (int l = 0; l < L_CHUNK; l += 8) {
        if (s_mask[l+0]) f4acc(a0, base[(size_t)(l+0) * D4]);
        if (s_mask[l+1]) f4acc(a1, base[(size_t)(l+1) * D4]);
        if (s_mask[l+2]) f4acc(a2, base[(size_t)(l+2) * D4]);
        if (s_mask[l+3]) f4acc(a3, base[(size_t)(l+3) * D4]);
        if (s_mask[l+4]) f4acc(a0, base[(size_t)(l+4) * D4]);
        if (s_mask[l+5]) f4acc(a1, base[(size_t)(l+5) * D4]);
        if (s_mask[l+6]) f4acc(a2, base[(size_t)(l+6) * D4]);
        if (s_mask[l+7]) f4acc(a3, base[(size_t)(l+7) * D4]);
    }
    f4acc(a0, a1); f4acc(a2, a3); f4acc(a0, a2);

    ((float4*)(g_partial + ((size_t)b * SPLIT + s) * D_DIM))[c4] = a0;
}

// ---------------- K2: fused reduce + normalize + heads (PDL) ---------------
__global__ __launch_bounds__(T3) void epilogue_kernel(
    const int*   __restrict__ mask,
    const float* __restrict__ W13,
    const float* __restrict__ b13,
    const float* __restrict__ W14,
    const float* __restrict__ b14,
    float*       __restrict__ out)
{
    const int b0   = blockIdx.x * BPB;        // batch group
    const int og   = blockIdx.y;              // output group
    const int tid  = threadIdx.x;
    const int lane = tid & 31;
    const int warp = tid >> 5;                // 0..7

    __shared__ float4 s_pooled[BPB][D4];      // 12 KB
    __shared__ int    s_cnt[BPB];
    __shared__ float  s_inv[BPB];

    const int o       = og * OPG + warp;
    const bool active = (o < N_OUT);

    // ---- Pre-sync work (independent of K1, overlaps its tail) ----
    float4 w[D4 / 32];
    float  bias = 0.f;
    if (active) {
        const float4* w4 = (const float4*)((o < 52) ? (W13 + (size_t)o * D_DIM)
                                                    : (W14 + (size_t)(o - 52) * D_DIM));
        bias = (o < 52) ? b13[o] : b14[o - 52];
        #pragma unroll
        for (int i = 0; i < D4 / 32; i++) w[i] = w4[lane + 32 * i];
    }

    if (tid < BPB) s_cnt[tid] = 0;
    __syncthreads();
    #pragma unroll
    for (int bi = 0; bi < BPB; bi++) {
        const int* mrow = mask + (b0 + bi) * L_DIM;
        int m = mrow[tid] + mrow[tid + 256];
        #pragma unroll
        for (int off = 16; off; off >>= 1)
            m += __shfl_down_sync(0xffffffffu, m, off);
        if (lane == 0) atomicAdd(&s_cnt[bi], m);
    }
    __syncthreads();
    if (tid < BPB) s_inv[tid] = 1.0f / (float)s_cnt[tid];
    __syncthreads();

    // ---- Wait for K1's partials ----
    cudaGridDependencySynchronize();

    // Reduce 8 partials for each of the 768 (batch, float4-col) pairs
    // (96 KB from L2 per block, 8-deep MLP per thread-item).
    #pragma unroll
    for (int k = 0; k < 3; k++) {
        int idx = tid + T3 * k;
        int bi = idx / D4, c4 = idx % D4;
        const float4* gp4 =
            (const float4*)(g_partial + (size_t)(b0 + bi) * SPLIT * D_DIM);
        float4 cs = make_float4(0.f,0.f,0.f,0.f);
        #pragma unroll
        for (int s = 0; s < SPLIT; s++)
            f4acc(cs, gp4[(size_t)s * D4 + c4]);
        float inv = s_inv[bi];
        cs.x *= inv; cs.y *= inv; cs.z *= inv; cs.w *= inv;
        s_pooled[bi][c4] = cs;
    }
    __syncthreads();

    if (!active) return;

    float acc[BPB] = {0.f, 0.f, 0.f, 0.f};
    #pragma unroll
    for (int i = 0; i < D4 / 32; i++) {
        #pragma unroll
        for (int bi = 0; bi < BPB; bi++) {
            float4 p = s_pooled[bi][lane + 32 * i];
            acc[bi] += w[i].x * p.x + w[i].y * p.y + w[i].z * p.z + w[i].w * p.w;
        }
    }
    #pragma unroll
    for (int off = 16; off; off >>= 1) {
        #pragma unroll
        for (int bi = 0; bi < BPB; bi++)
            acc[bi] += __shfl_down_sync(0xffffffffu, acc[bi], off);
    }
    if (lane == 0) {
        #pragma unroll
        for (int bi = 0; bi < BPB; bi++)
            out[(b0 + bi) * N_OUT + o] = acc[bi] + bias;
    }
}

extern "C" void kernel_launch(void* const* d_in, const int* in_sizes, int n_in,
                              void* d_out, int out_size)
{
    const float* fh   = (const float*)d_in[0];
    const int*   mask = (const int*)d_in[1];
    const float* W13  = (const float*)d_in[2];
    const float* b13  = (const float*)d_in[3];
    const float* W14  = (const float*)d_in[4];
    const float* b14  = (const float*)d_in[5];
    float* out = (float*)d_out;

    dim3 grid1(SPLIT, B_DIM);
    pool_partial_kernel<<<grid1, T1>>>(fh, mask);

    cudaLaunchAttribute attr[1];
    attr[0].id = cudaLaunchAttributeProgrammaticStreamSerialization;
    attr[0].val.programmaticStreamSerializationAllowed = 1;

    cudaLaunchConfig_t cfg = {};
    cfg.gridDim = dim3(NBG, OGRP);
    cfg.blockDim = dim3(T3);
    cfg.attrs = attr;
    cfg.numAttrs = 1;
    cudaLaunchKernelEx(&cfg, epilogue_kernel, mask, W13, b13, W14, b14, out);
}